// round 1
// baseline (speedup 1.0000x reference)
#include <cuda_runtime.h>
#include <math.h>

#define N_LI 8192
#define N_RA 2048
#define N_Q  (N_LI + N_RA)
#define M_PTS 2048
#define SLICES 8
#define TPB 256
#define QPB (TPB / SLICES)   // 32 queries per block
#define GRIDW 513

// One thread per (query, candidate-slice). Each block:
//  1) compacts dynamic candidates (|ra_pts[:,4]| > 0.1) into shared as
//     float4{px, py, px^2+py^2, 0}, padded to a multiple of 32 with sentinels
//  2) hot loop: per candidate, 3+9 FFMA + 9 FMNMX covering all 9 neighbors
//     using min_p [p2 - 2 x_a px - 2 y_b py]  (exact integer fp32 arithmetic)
//  3) butterfly-min across the 8 slices, lane s==0 writes the 9 outputs
__global__ __launch_bounds__(TPB, 1) void gauss_map_kernel(
    const int* __restrict__ li_coors,
    const int* __restrict__ ra_coors,
    const float* __restrict__ ra_pts,
    const int* __restrict__ ra_vox,
    float* __restrict__ out)
{
    __shared__ float4 cand[M_PTS + 32];
    __shared__ int s_cnt;
    const int tid = threadIdx.x;
    if (tid == 0) s_cnt = 0;
    __syncthreads();

    // ---- per-block compaction of dynamic candidates ----
    #pragma unroll
    for (int it = 0; it < M_PTS / TPB; it++) {
        int i = it * TPB + tid;
        float v = ra_pts[i * 5 + 4];
        if (fabsf(v) > 0.1f) {
            float px = (float)ra_vox[i * 3 + 1];
            float py = (float)ra_vox[i * 3 + 2];
            int idx = atomicAdd(&s_cnt, 1);
            cand[idx] = make_float4(px, py, fmaf(px, px, py * py), 0.0f);
        }
    }
    __syncthreads();
    const int cnt = s_cnt;
    const int cnt_pad = (cnt + 31) & ~31;
    for (int i = cnt + tid; i < cnt_pad; i += TPB)
        cand[i] = make_float4(1.0e9f, 1.0e9f, 2.0e18f, 0.0f);  // sentinel: never the min
    __syncthreads();

    // ---- query / neighbor setup ----
    const int s = tid & (SLICES - 1);
    const int q = blockIdx.x * QPB + (tid >> 3);

    int x, y;
    if (q < N_LI) { x = li_coors[2 * q];            y = li_coors[2 * q + 1]; }
    else          { int r = q - N_LI; x = ra_coors[2 * r]; y = ra_coors[2 * r + 1]; }

    int xm = x - 1; if (xm < 0)      xm += GRIDW;
    int xp = x + 1; if (xp >= GRIDW) xp -= GRIDW;
    int ym = y - 1; if (ym < 0)      ym += GRIDW;
    int yp = y + 1; if (yp >= GRIDW) yp -= GRIDW;

    // INDEX_SHIFT order: dim0 shift cycles {0,-1,+1} (a = j%3),
    //                    dim1 shift is    {0,+1,-1} (b = j/3)
    const float xa0 = (float)x,  xa1 = (float)xm, xa2 = (float)xp;
    const float yb0 = (float)y,  yb1 = (float)yp, yb2 = (float)ym;
    const float n2x0 = -2.0f * xa0, n2x1 = -2.0f * xa1, n2x2 = -2.0f * xa2;
    const float n2y0 = -2.0f * yb0, n2y1 = -2.0f * yb1, n2y2 = -2.0f * yb2;

    float mn[9];
    #pragma unroll
    for (int j = 0; j < 9; j++) mn[j] = 3.0e38f;

    // ---- hot loop: 12 FFMA + 9 FMNMX + 1 LDS.128 per candidate ----
    const float4* __restrict__ cp = cand + s;
    const int iters = cnt_pad >> 3;   // multiple of 4
    #pragma unroll 4
    for (int k = 0; k < iters; k++) {
        const float4 c = cp[k * SLICES];
        const float w0 = fmaf(n2y0, c.y, c.z);
        const float w1 = fmaf(n2y1, c.y, c.z);
        const float w2 = fmaf(n2y2, c.y, c.z);
        mn[0] = fminf(mn[0], fmaf(n2x0, c.x, w0));
        mn[1] = fminf(mn[1], fmaf(n2x1, c.x, w0));
        mn[2] = fminf(mn[2], fmaf(n2x2, c.x, w0));
        mn[3] = fminf(mn[3], fmaf(n2x0, c.x, w1));
        mn[4] = fminf(mn[4], fmaf(n2x1, c.x, w1));
        mn[5] = fminf(mn[5], fmaf(n2x2, c.x, w1));
        mn[6] = fminf(mn[6], fmaf(n2x0, c.x, w2));
        mn[7] = fminf(mn[7], fmaf(n2x1, c.x, w2));
        mn[8] = fminf(mn[8], fmaf(n2x2, c.x, w2));
    }

    // ---- reduce across the 8 slices of this query (groups of 8 lanes) ----
    #pragma unroll
    for (int j = 0; j < 9; j++) {
        float v = mn[j];
        v = fminf(v, __shfl_xor_sync(0xffffffffu, v, 1));
        v = fminf(v, __shfl_xor_sync(0xffffffffu, v, 2));
        v = fminf(v, __shfl_xor_sync(0xffffffffu, v, 4));
        mn[j] = v;
    }

    if (s == 0) {
        const float x2[3] = {xa0 * xa0, xa1 * xa1, xa2 * xa2};
        const float y2[3] = {yb0 * yb0, yb1 * yb1, yb2 * yb2};
        const bool active = cnt > 1;   // reference: use = (sum(dy_mask) > 1)
        float* o = out + (size_t)q * 9;   // li rows then ra rows: contiguous in q
        #pragma unroll
        for (int j = 0; j < 9; j++) {
            float d2 = mn[j] + x2[j % 3] + y2[j / 3];
            o[j] = active ? 0.01f * sqrtf(fmaxf(d2, 0.0f)) : 0.0f;
        }
    }
}

extern "C" void kernel_launch(void* const* d_in, const int* in_sizes, int n_in,
                              void* d_out, int out_size) {
    const int*   li  = (const int*)d_in[0];
    const int*   ra  = (const int*)d_in[1];
    const float* pts = (const float*)d_in[2];
    const int*   vox = (const int*)d_in[3];
    float* out = (float*)d_out;
    gauss_map_kernel<<<N_Q / QPB, TPB>>>(li, ra, pts, vox, out);
}

// round 2
// speedup vs baseline: 1.0804x; 1.0804x over previous
#include <cuda_runtime.h>
#include <math.h>

#define N_LI 8192
#define N_RA 2048
#define N_Q  (N_LI + N_RA)
#define M_PTS 2048
#define SLICES 16
#define TPB 256
#define QPB (TPB / SLICES)   // 16 queries per block
#define GRIDW 513
#define MAXC 2112            // 2048 padded up to multiple of 64

// f32x2 packed helpers (Blackwell FFMA2 path — PTX only, ptxas won't auto-fuse)
__device__ __forceinline__ unsigned long long pack2(float lo, float hi) {
    unsigned long long r;
    asm("mov.b64 %0, {%1, %2};" : "=l"(r) : "f"(lo), "f"(hi));
    return r;
}
#define FMA2(d, a, b, c) asm("fma.rn.f32x2 %0, %1, %2, %3;" : "=l"(d) : "l"(a), "l"(b), "l"(c))
#define UNPK(lo, hi, v)  asm("mov.b64 {%0, %1}, %2;" : "=f"(lo), "=f"(hi) : "l"(v))

// One thread per (query, candidate-pair-slice).
//  1) ballot-aggregated compaction of dynamic candidates into SoA smem
//     (px[], py[], p2[]), sentinel-padded to a multiple of 64
//  2) hot loop per candidate PAIR: 12 fma.f32x2 + 18 FMNMX + 3 LDS.64
//     using d2 = [p2 - 2 x_a px - 2 y_b py] + (x_a^2 + y_b^2)  (int-exact fp32)
//  3) butterfly-min over 16 slices, lane s==0 writes 9 outputs
__global__ __launch_bounds__(TPB, 4) void gauss_map_kernel(
    const int* __restrict__ li_coors,
    const int* __restrict__ ra_coors,
    const float* __restrict__ ra_pts,
    const int* __restrict__ ra_vox,
    float* __restrict__ out)
{
    __shared__ __align__(16) float s_px[MAXC];
    __shared__ __align__(16) float s_py[MAXC];
    __shared__ __align__(16) float s_p2[MAXC];
    __shared__ int s_cnt;
    const int tid  = threadIdx.x;
    const int lane = tid & 31;
    if (tid == 0) s_cnt = 0;
    __syncthreads();

    // ---- ballot-aggregated compaction ----
    const unsigned FULL = 0xffffffffu;
    #pragma unroll
    for (int it = 0; it < M_PTS / TPB; it++) {
        int i = it * TPB + tid;
        bool pass = fabsf(ra_pts[i * 5 + 4]) > 0.1f;
        unsigned m = __ballot_sync(FULL, pass);
        int base;
        if (lane == 0) base = atomicAdd(&s_cnt, __popc(m));
        base = __shfl_sync(FULL, base, 0);
        if (pass) {
            int idx = base + __popc(m & ((1u << lane) - 1u));
            float px = (float)ra_vox[i * 3 + 1];
            float py = (float)ra_vox[i * 3 + 2];
            s_px[idx] = px;
            s_py[idx] = py;
            s_p2[idx] = fmaf(px, px, py * py);
        }
    }
    __syncthreads();
    const int cnt = s_cnt;
    const int cnt_pad = (cnt + 63) & ~63;
    for (int i = cnt + tid; i < cnt_pad; i += TPB) {
        s_px[i] = 1.0e9f; s_py[i] = 1.0e9f; s_p2[i] = 2.0e18f;  // never the min
    }
    __syncthreads();

    // ---- query / neighbor setup ----
    const int s = tid & (SLICES - 1);
    const int q = blockIdx.x * QPB + (tid >> 4);

    int x, y;
    if (q < N_LI) { x = li_coors[2 * q];            y = li_coors[2 * q + 1]; }
    else          { int r = q - N_LI; x = ra_coors[2 * r]; y = ra_coors[2 * r + 1]; }

    int xm = x - 1; if (xm < 0)      xm += GRIDW;
    int xp = x + 1; if (xp >= GRIDW) xp -= GRIDW;
    int ym = y - 1; if (ym < 0)      ym += GRIDW;
    int yp = y + 1; if (yp >= GRIDW) yp -= GRIDW;

    // INDEX_SHIFT: dim0 shift cycles {0,-1,+1} (a = j%3), dim1 {0,+1,-1} (b = j/3)
    const float xa0 = (float)x,  xa1 = (float)xm, xa2 = (float)xp;
    const float yb0 = (float)y,  yb1 = (float)yp, yb2 = (float)ym;
    const unsigned long long n2x[3] = { pack2(-2.0f * xa0, -2.0f * xa0),
                                        pack2(-2.0f * xa1, -2.0f * xa1),
                                        pack2(-2.0f * xa2, -2.0f * xa2) };
    const unsigned long long n2y[3] = { pack2(-2.0f * yb0, -2.0f * yb0),
                                        pack2(-2.0f * yb1, -2.0f * yb1),
                                        pack2(-2.0f * yb2, -2.0f * yb2) };

    float mn[9];
    #pragma unroll
    for (int j = 0; j < 9; j++) mn[j] = 3.0e38f;

    const unsigned long long* __restrict__ px2 = (const unsigned long long*)s_px;
    const unsigned long long* __restrict__ py2 = (const unsigned long long*)s_py;
    const unsigned long long* __restrict__ p22 = (const unsigned long long*)s_p2;

    // ---- hot loop: per pair, 12 fma.f32x2 + 18 FMNMX + 3 LDS.64 ----
    const int iters = cnt_pad >> 5;   // pairs/SLICES; multiple of 2
    #pragma unroll 2
    for (int k = 0; k < iters; k++) {
        const int j = k * SLICES + s;
        const unsigned long long cx = px2[j];
        const unsigned long long cy = py2[j];
        const unsigned long long cz = p22[j];
        unsigned long long w[3];
        FMA2(w[0], n2y[0], cy, cz);
        FMA2(w[1], n2y[1], cy, cz);
        FMA2(w[2], n2y[2], cy, cz);
        #pragma unroll
        for (int b = 0; b < 3; b++) {
            #pragma unroll
            for (int a = 0; a < 3; a++) {
                unsigned long long t;
                FMA2(t, n2x[a], cx, w[b]);
                float tl, th;
                UNPK(tl, th, t);
                mn[b * 3 + a] = fminf(mn[b * 3 + a], fminf(tl, th));
            }
        }
    }

    // ---- reduce across the 16 slices of this query ----
    #pragma unroll
    for (int j = 0; j < 9; j++) {
        float v = mn[j];
        v = fminf(v, __shfl_xor_sync(FULL, v, 1));
        v = fminf(v, __shfl_xor_sync(FULL, v, 2));
        v = fminf(v, __shfl_xor_sync(FULL, v, 4));
        v = fminf(v, __shfl_xor_sync(FULL, v, 8));
        mn[j] = v;
    }

    if (s == 0) {
        const float x2[3] = {xa0 * xa0, xa1 * xa1, xa2 * xa2};
        const float y2[3] = {yb0 * yb0, yb1 * yb1, yb2 * yb2};
        const bool active = cnt > 1;   // reference: use = (sum(dy_mask) > 1)
        float* o = out + (size_t)q * 9;
        #pragma unroll
        for (int j = 0; j < 9; j++) {
            float d2 = mn[j] + x2[j % 3] + y2[j / 3];
            o[j] = active ? 0.01f * sqrtf(fmaxf(d2, 0.0f)) : 0.0f;
        }
    }
}

extern "C" void kernel_launch(void* const* d_in, const int* in_sizes, int n_in,
                              void* d_out, int out_size) {
    const int*   li  = (const int*)d_in[0];
    const int*   ra  = (const int*)d_in[1];
    const float* pts = (const float*)d_in[2];
    const int*   vox = (const int*)d_in[3];
    float* out = (float*)d_out;
    gauss_map_kernel<<<N_Q / QPB, TPB>>>(li, ra, pts, vox, out);
}

// round 3
// speedup vs baseline: 1.1764x; 1.0889x over previous
#include <cuda_runtime.h>
#include <math.h>

#define N_LI 8192
#define N_RA 2048
#define N_Q  (N_LI + N_RA)
#define M_PTS 2048
#define GRIDW 513

#define TSH   5                 // 32-wide tiles
#define TILES_X 16
#define TILES (TILES_X * TILES_X)
#define QCAP  1024              // queries per tile cap (mean ~40)
#define SCAP  256               // wrapped-query cap (mean ~40)
#define CCAP  2048
#define SLOW_BLOCKS 8           // 8 blocks x 4 warps = 32 warps for slow queries

// scratch (device globals: no allocation allowed)
__device__ float4 g_cand[CCAP];
__device__ int    g_ccnt;
__device__ int    g_scnt;
__device__ int    g_slow[SCAP];
__device__ int    g_qbin[TILES * QCAP];
__device__ int    g_qcnt[TILES];

// ---------------- K1: compact candidates + bin queries ----------------
__global__ __launch_bounds__(1024, 1) void k1_prep(
    const int* __restrict__ li, const int* __restrict__ ra,
    const float* __restrict__ pts, const int* __restrict__ vox)
{
    __shared__ int s_qc[TILES];
    __shared__ int s_cc, s_sc;
    const int tid = threadIdx.x;
    if (tid < TILES) s_qc[tid] = 0;
    if (tid == 0) { s_cc = 0; s_sc = 0; }
    __syncthreads();

    // dynamic candidates: |ra_pts[:,4]| > 0.1 -> (px, py, px^2+py^2)
    #pragma unroll
    for (int it = 0; it < M_PTS / 1024; it++) {
        int i = it * 1024 + tid;
        if (fabsf(pts[i * 5 + 4]) > 0.1f) {
            float px = (float)vox[i * 3 + 1];
            float py = (float)vox[i * 3 + 2];
            int idx = atomicAdd(&s_cc, 1);
            g_cand[idx] = make_float4(px, py, fmaf(px, px, py * py), 0.0f);
        }
    }
    // bin queries by tile; wrap-risk queries (x==0||y==0) go to the slow list
    #pragma unroll
    for (int it = 0; it < N_Q / 1024; it++) {
        int q = it * 1024 + tid;
        int x, y;
        if (q < N_LI) { x = li[2 * q];             y = li[2 * q + 1]; }
        else          { int r = q - N_LI; x = ra[2 * r]; y = ra[2 * r + 1]; }
        if (x == 0 || y == 0 || x > 511 || y > 511) {
            int idx = atomicAdd(&s_sc, 1);
            if (idx < SCAP) g_slow[idx] = q;
        } else {
            int t = ((y >> TSH) << 4) + (x >> TSH);
            int idx = atomicAdd(&s_qc[t], 1);
            if (idx < QCAP) g_qbin[t * QCAP + idx] = q;
        }
    }
    __syncthreads();
    if (tid < TILES) g_qcnt[tid] = min(s_qc[tid], QCAP);
    if (tid == 0) { g_ccnt = s_cc; g_scnt = min(s_sc, SCAP); }
}

// ---------------- K2: per-tile filter + query evaluation (+ slow path) ----------------
__global__ __launch_bounds__(128, 2) void k2_main(
    const int* __restrict__ li, const int* __restrict__ ra,
    float* __restrict__ out)
{
    __shared__ __align__(16) float4 s_c[CCAP];   // filtered candidates
    __shared__ float s_wmin[4];
    __shared__ float s_thr;
    __shared__ int   s_cnt;

    const int b    = blockIdx.x;
    const int tid  = threadIdx.x;
    const int lane = tid & 31;
    const unsigned FULL = 0xffffffffu;
    const int cc   = g_ccnt;
    const bool active = cc > 1;    // reference: use = sum(dy_mask) > 1

    if (b < TILES) {
        // ===== fast tiles =====
        const int qn = g_qcnt[b];
        if (qn == 0) return;

        int cn = 0;
        if (active) {
            const float refx = (float)((b & 15) << TSH) + 15.5f;
            const float refy = (float)((b >> 4) << TSH) + 15.5f;
            // pass 1: Umin = min distance from ref to any candidate
            float mv = 3.0e38f;
            for (int i = tid; i < cc; i += 128) {
                float4 c = g_cand[i];
                float dx = c.x - refx, dy = c.y - refy;
                mv = fminf(mv, fmaf(dx, dx, dy * dy));
            }
            #pragma unroll
            for (int o = 16; o; o >>= 1) mv = fminf(mv, __shfl_xor_sync(FULL, mv, o));
            if (lane == 0) s_wmin[tid >> 5] = mv;
            if (tid == 0) s_cnt = 0;
            __syncthreads();
            if (tid == 0) {
                float m = fminf(fminf(s_wmin[0], s_wmin[1]), fminf(s_wmin[2], s_wmin[3]));
                // keep c iff d(ref,c) <= Umin + 2R  (R = 16.5*sqrt(2) half-diag of 34x34 box)
                float u = sqrtf(m) + 2.0f * 23.3345f + 1.0f;   // +1 slack for fp rounding
                s_thr = u * u;
            }
            __syncthreads();
            const float thr = s_thr;
            // pass 2: ballot-compact kept candidates into smem
            for (int i0 = 0; i0 < cc; i0 += 128) {
                int i = i0 + tid;
                bool keep = false; float4 c;
                if (i < cc) {
                    c = g_cand[i];
                    float dx = c.x - refx, dy = c.y - refy;
                    keep = fmaf(dx, dx, dy * dy) <= thr;
                }
                unsigned m = __ballot_sync(FULL, keep);
                int base;
                if (lane == 0) base = atomicAdd(&s_cnt, __popc(m));
                base = __shfl_sync(FULL, base, 0);
                if (keep) s_c[base + __popc(m & ((1u << lane) - 1u))] = c;
            }
            __syncthreads();
            cn = s_cnt;
        }

        // each thread: one query, all 9 neighbors (no wrap: x,y in [1,511])
        for (int qi = tid; qi < qn; qi += 128) {
            const int q = g_qbin[b * QCAP + qi];
            int x, y;
            if (q < N_LI) { x = li[2 * q];             y = li[2 * q + 1]; }
            else          { int r = q - N_LI; x = ra[2 * r]; y = ra[2 * r + 1]; }
            // INDEX_SHIFT: dim0 {0,-1,+1} (a=j%3), dim1 {0,+1,-1} (b=j/3)
            const float xa0 = (float)x, xa1 = (float)(x - 1), xa2 = (float)(x + 1);
            const float yb0 = (float)y, yb1 = (float)(y + 1), yb2 = (float)(y - 1);
            const float n2x0 = -2.0f * xa0, n2x1 = -2.0f * xa1, n2x2 = -2.0f * xa2;
            const float n2y0 = -2.0f * yb0, n2y1 = -2.0f * yb1, n2y2 = -2.0f * yb2;
            float mn[9];
            #pragma unroll
            for (int j = 0; j < 9; j++) mn[j] = 3.0e38f;
            #pragma unroll 2
            for (int k = 0; k < cn; k++) {
                const float4 c = s_c[k];           // broadcast LDS.128
                const float w0 = fmaf(n2y0, c.y, c.z);
                const float w1 = fmaf(n2y1, c.y, c.z);
                const float w2 = fmaf(n2y2, c.y, c.z);
                mn[0] = fminf(mn[0], fmaf(n2x0, c.x, w0));
                mn[1] = fminf(mn[1], fmaf(n2x1, c.x, w0));
                mn[2] = fminf(mn[2], fmaf(n2x2, c.x, w0));
                mn[3] = fminf(mn[3], fmaf(n2x0, c.x, w1));
                mn[4] = fminf(mn[4], fmaf(n2x1, c.x, w1));
                mn[5] = fminf(mn[5], fmaf(n2x2, c.x, w1));
                mn[6] = fminf(mn[6], fmaf(n2x0, c.x, w2));
                mn[7] = fminf(mn[7], fmaf(n2x1, c.x, w2));
                mn[8] = fminf(mn[8], fmaf(n2x2, c.x, w2));
            }
            const float x2[3] = {xa0 * xa0, xa1 * xa1, xa2 * xa2};
            const float y2[3] = {yb0 * yb0, yb1 * yb1, yb2 * yb2};
            float* o = out + (size_t)q * 9;
            #pragma unroll
            for (int j = 0; j < 9; j++) {
                float d2 = mn[j] + x2[j % 3] + y2[j / 3];
                o[j] = active ? 0.01f * sqrtf(fmaxf(d2, 0.0f)) : 0.0f;
            }
        }
    } else {
        // ===== slow path: one warp per wrapped query, full candidate list =====
        const int wg = (b - TILES) * 4 + (tid >> 5);   // global warp id 0..31
        const int sc = g_scnt;
        for (int si = wg; si < sc; si += SLOW_BLOCKS * 4) {
            const int q = g_slow[si];
            int x, y;
            if (q < N_LI) { x = li[2 * q];             y = li[2 * q + 1]; }
            else          { int r = q - N_LI; x = ra[2 * r]; y = ra[2 * r + 1]; }
            int xm = x - 1; if (xm < 0)      xm += GRIDW;
            int xp = x + 1; if (xp >= GRIDW) xp -= GRIDW;
            int ym = y - 1; if (ym < 0)      ym += GRIDW;
            int yp = y + 1; if (yp >= GRIDW) yp -= GRIDW;
            const float xa0 = (float)x,  xa1 = (float)xm, xa2 = (float)xp;
            const float yb0 = (float)y,  yb1 = (float)yp, yb2 = (float)ym;
            const float n2x0 = -2.0f * xa0, n2x1 = -2.0f * xa1, n2x2 = -2.0f * xa2;
            const float n2y0 = -2.0f * yb0, n2y1 = -2.0f * yb1, n2y2 = -2.0f * yb2;
            float mn[9];
            #pragma unroll
            for (int j = 0; j < 9; j++) mn[j] = 3.0e38f;
            for (int k = lane; k < cc; k += 32) {
                const float4 c = g_cand[k];
                const float w0 = fmaf(n2y0, c.y, c.z);
                const float w1 = fmaf(n2y1, c.y, c.z);
                const float w2 = fmaf(n2y2, c.y, c.z);
                mn[0] = fminf(mn[0], fmaf(n2x0, c.x, w0));
                mn[1] = fminf(mn[1], fmaf(n2x1, c.x, w0));
                mn[2] = fminf(mn[2], fmaf(n2x2, c.x, w0));
                mn[3] = fminf(mn[3], fmaf(n2x0, c.x, w1));
                mn[4] = fminf(mn[4], fmaf(n2x1, c.x, w1));
                mn[5] = fminf(mn[5], fmaf(n2x2, c.x, w1));
                mn[6] = fminf(mn[6], fmaf(n2x0, c.x, w2));
                mn[7] = fminf(mn[7], fmaf(n2x1, c.x, w2));
                mn[8] = fminf(mn[8], fmaf(n2x2, c.x, w2));
            }
            #pragma unroll
            for (int j = 0; j < 9; j++) {
                float v = mn[j];
                #pragma unroll
                for (int o = 16; o; o >>= 1) v = fminf(v, __shfl_xor_sync(FULL, v, o));
                mn[j] = v;
            }
            if (lane == 0) {
                const float x2[3] = {xa0 * xa0, xa1 * xa1, xa2 * xa2};
                const float y2[3] = {yb0 * yb0, yb1 * yb1, yb2 * yb2};
                float* o = out + (size_t)q * 9;
                #pragma unroll
                for (int j = 0; j < 9; j++) {
                    float d2 = mn[j] + x2[j % 3] + y2[j / 3];
                    o[j] = active ? 0.01f * sqrtf(fmaxf(d2, 0.0f)) : 0.0f;
                }
            }
        }
    }
}

extern "C" void kernel_launch(void* const* d_in, const int* in_sizes, int n_in,
                              void* d_out, int out_size) {
    const int*   li  = (const int*)d_in[0];
    const int*   ra  = (const int*)d_in[1];
    const float* pts = (const float*)d_in[2];
    const int*   vox = (const int*)d_in[3];
    float* out = (float*)d_out;
    k1_prep<<<1, 1024>>>(li, ra, pts, vox);
    k2_main<<<TILES + SLOW_BLOCKS, 128>>>(li, ra, out);
}

// round 4
// speedup vs baseline: 1.7945x; 1.5254x over previous
#include <cuda_runtime.h>
#include <math.h>

#define N_LI 8192
#define N_RA 2048
#define N_Q  (N_LI + N_RA)
#define M_PTS 2048
#define GRIDW 513
#define TSH 5                  // 32-wide tiles
#define TILES 256
#define SEGS 8
#define SEGQ (N_Q / SEGS)      // 1280 queries per binning segment
#define SEGCAP 96              // per (tile, segment) cap; mean ~5
#define SLOWCAP 64             // per-segment wrapped-query cap; mean ~5
#define SLOW_BLOCKS 4
#define TWO_R_SLACK 47.6691f   // 2 * 16.5*sqrt(2) + 1.0 slack

// scratch (device globals; no cross-launch state needed: everything below is
// either written fresh by plain stores each launch, or guarded by counts that
// are themselves plain-stored each launch)
__device__ float4 g_cand[M_PTS];
__device__ int    g_ccnt;
__device__ float  g_thr[TILES];
__device__ int    g_qbin[TILES][SEGS][SEGCAP];
__device__ int    g_qcnt[TILES][SEGS];
__device__ int    g_slow[SEGS][SLOWCAP];
__device__ int    g_scnt[SEGS];

// ---------------- K1: three independent parallel tasks ----------------
//   blocks [0,8):    bin queries of segment b into per-tile per-segment lists
//   block  8:        compact dynamic candidates -> g_cand
//   blocks [9,265):  per-tile pruning threshold from RAW inputs (no dependency
//                    on compaction): thr = (sqrt(min d2(ref,c)) + 2R + 1)^2
__global__ __launch_bounds__(256, 4) void k1_prep(
    const int* __restrict__ li, const int* __restrict__ ra,
    const float* __restrict__ pts, const int* __restrict__ vox)
{
    const int b = blockIdx.x, tid = threadIdx.x, lane = tid & 31;
    const unsigned FULL = 0xffffffffu;

    if (b < SEGS) {
        // ---- query binning (shared counters only) ----
        __shared__ int s_qc[TILES];
        __shared__ int s_sc;
        if (tid < TILES) s_qc[tid] = 0;
        if (tid == 0) s_sc = 0;
        __syncthreads();
        #pragma unroll
        for (int it = 0; it < SEGQ / 256; it++) {
            int q = b * SEGQ + it * 256 + tid;
            int x, y;
            if (q < N_LI) { x = li[2 * q];             y = li[2 * q + 1]; }
            else          { int r = q - N_LI; x = ra[2 * r]; y = ra[2 * r + 1]; }
            if (x == 0 || y == 0) {                 // wrap risk -> slow list
                int idx = atomicAdd(&s_sc, 1);
                if (idx < SLOWCAP) g_slow[b][idx] = q;
            } else {
                int t = ((y >> TSH) << 4) | (x >> TSH);
                int idx = atomicAdd(&s_qc[t], 1);
                if (idx < SEGCAP) g_qbin[t][b][idx] = q;
            }
        }
        __syncthreads();
        if (tid < TILES) g_qcnt[tid][b] = min(s_qc[tid], SEGCAP);
        if (tid == 0) g_scnt[b] = min(s_sc, SLOWCAP);
    } else if (b == SEGS) {
        // ---- candidate compaction ----
        __shared__ int s_cc;
        if (tid == 0) s_cc = 0;
        __syncthreads();
        #pragma unroll
        for (int it = 0; it < M_PTS / 256; it++) {
            int i = it * 256 + tid;
            bool pass = fabsf(pts[i * 5 + 4]) > 0.1f;
            unsigned m = __ballot_sync(FULL, pass);
            int base;
            if (lane == 0) base = atomicAdd(&s_cc, __popc(m));
            base = __shfl_sync(FULL, base, 0);
            if (pass) {
                float px = (float)vox[i * 3 + 1];
                float py = (float)vox[i * 3 + 2];
                g_cand[base + __popc(m & ((1u << lane) - 1u))] =
                    make_float4(px, py, fmaf(px, px, py * py), 0.0f);
            }
        }
        __syncthreads();
        if (tid == 0) g_ccnt = s_cc;
    } else {
        // ---- per-tile threshold ----
        const int t = b - SEGS - 1;
        const float refx = (float)((t & 15) << TSH) + 15.5f;
        const float refy = (float)((t >> 4) << TSH) + 15.5f;
        float mv = 3.0e38f;
        #pragma unroll
        for (int it = 0; it < M_PTS / 256; it++) {
            int i = it * 256 + tid;
            if (fabsf(pts[i * 5 + 4]) > 0.1f) {
                float dx = (float)vox[i * 3 + 1] - refx;
                float dy = (float)vox[i * 3 + 2] - refy;
                mv = fminf(mv, fmaf(dx, dx, dy * dy));
            }
        }
        __shared__ float s_m[8];
        #pragma unroll
        for (int o = 16; o; o >>= 1) mv = fminf(mv, __shfl_xor_sync(FULL, mv, o));
        if (lane == 0) s_m[tid >> 5] = mv;
        __syncthreads();
        if (tid == 0) {
            float m = s_m[0];
            #pragma unroll
            for (int i = 1; i < 8; i++) m = fminf(m, s_m[i]);
            float u = sqrtf(m) + TWO_R_SLACK;
            g_thr[t] = u * u;
        }
    }
}

// ---------------- K2: single-pass filter + query eval (+ slow path) ----------------
__global__ __launch_bounds__(256, 2) void k2_main(
    const int* __restrict__ li, const int* __restrict__ ra,
    float* __restrict__ out)
{
    const int b = blockIdx.x, tid = threadIdx.x, lane = tid & 31;
    const unsigned FULL = 0xffffffffu;
    const int cc = g_ccnt;
    const bool active = cc > 1;          // reference: use = sum(dy_mask) > 1

    if (b < TILES) {
        __shared__ __align__(16) float4 s_c[M_PTS];
        __shared__ int s_cnt;
        __shared__ int s_off[SEGS + 1];
        if (tid == 0) {
            s_cnt = 0;
            int a = 0;
            #pragma unroll
            for (int i = 0; i < SEGS; i++) { s_off[i] = a; a += g_qcnt[b][i]; }
            s_off[SEGS] = a;
        }
        __syncthreads();
        const int qn = s_off[SEGS];
        if (qn == 0) return;

        // ---- single-pass filter with precomputed threshold ----
        int cn = 0;
        if (active) {
            const float refx = (float)((b & 15) << TSH) + 15.5f;
            const float refy = (float)((b >> 4) << TSH) + 15.5f;
            const float thr = g_thr[b];
            for (int i0 = 0; i0 < cc; i0 += 256) {
                int i = i0 + tid;
                float4 c; bool keep = false;
                if (i < cc) {
                    c = g_cand[i];
                    float dx = c.x - refx, dy = c.y - refy;
                    keep = fmaf(dx, dx, dy * dy) <= thr;
                }
                unsigned m = __ballot_sync(FULL, keep);
                int base;
                if (lane == 0) base = atomicAdd(&s_cnt, __popc(m));
                base = __shfl_sync(FULL, base, 0);
                if (keep) s_c[base + __popc(m & ((1u << lane) - 1u))] = c;
            }
            __syncthreads();
            cn = s_cnt;
        }

        // ---- one thread per query, 9 outputs (no wrap in fast tiles) ----
        for (int qi = tid; qi < qn; qi += 256) {
            int seg = 0;
            #pragma unroll
            for (int i = 1; i < SEGS; i++) if (qi >= s_off[i]) seg = i;
            const int q = g_qbin[b][seg][qi - s_off[seg]];
            int x, y;
            if (q < N_LI) { x = li[2 * q];             y = li[2 * q + 1]; }
            else          { int r = q - N_LI; x = ra[2 * r]; y = ra[2 * r + 1]; }
            // INDEX_SHIFT: dim0 {0,-1,+1} (a=j%3), dim1 {0,+1,-1} (b=j/3)
            const float xa0 = (float)x, xa1 = (float)(x - 1), xa2 = (float)(x + 1);
            const float yb0 = (float)y, yb1 = (float)(y + 1), yb2 = (float)(y - 1);
            const float n2x0 = -2.0f * xa0, n2x1 = -2.0f * xa1, n2x2 = -2.0f * xa2;
            const float n2y0 = -2.0f * yb0, n2y1 = -2.0f * yb1, n2y2 = -2.0f * yb2;
            float mn[9];
            #pragma unroll
            for (int j = 0; j < 9; j++) mn[j] = 3.0e38f;
            #pragma unroll 2
            for (int k = 0; k < cn; k++) {
                const float4 c = s_c[k];            // broadcast LDS.128
                const float w0 = fmaf(n2y0, c.y, c.z);
                const float w1 = fmaf(n2y1, c.y, c.z);
                const float w2 = fmaf(n2y2, c.y, c.z);
                mn[0] = fminf(mn[0], fmaf(n2x0, c.x, w0));
                mn[1] = fminf(mn[1], fmaf(n2x1, c.x, w0));
                mn[2] = fminf(mn[2], fmaf(n2x2, c.x, w0));
                mn[3] = fminf(mn[3], fmaf(n2x0, c.x, w1));
                mn[4] = fminf(mn[4], fmaf(n2x1, c.x, w1));
                mn[5] = fminf(mn[5], fmaf(n2x2, c.x, w1));
                mn[6] = fminf(mn[6], fmaf(n2x0, c.x, w2));
                mn[7] = fminf(mn[7], fmaf(n2x1, c.x, w2));
                mn[8] = fminf(mn[8], fmaf(n2x2, c.x, w2));
            }
            const float x2[3] = {xa0 * xa0, xa1 * xa1, xa2 * xa2};
            const float y2[3] = {yb0 * yb0, yb1 * yb1, yb2 * yb2};
            float* o = out + (size_t)q * 9;
            #pragma unroll
            for (int j = 0; j < 9; j++) {
                float d2 = mn[j] + x2[j % 3] + y2[j / 3];
                o[j] = active ? 0.01f * sqrtf(fmaxf(d2, 0.0f)) : 0.0f;
            }
        }
    } else {
        // ---- slow path: one warp per wrapped query, full candidate list ----
        __shared__ int s_soff[SEGS + 1];
        if (tid == 0) {
            int a = 0;
            #pragma unroll
            for (int i = 0; i < SEGS; i++) { s_soff[i] = a; a += g_scnt[i]; }
            s_soff[SEGS] = a;
        }
        __syncthreads();
        const int total = s_soff[SEGS];
        const int wg = (b - TILES) * 8 + (tid >> 5);
        for (int si = wg; si < total; si += SLOW_BLOCKS * 8) {
            int seg = 0;
            #pragma unroll
            for (int i = 1; i < SEGS; i++) if (si >= s_soff[i]) seg = i;
            const int q = g_slow[seg][si - s_soff[seg]];
            int x, y;
            if (q < N_LI) { x = li[2 * q];             y = li[2 * q + 1]; }
            else          { int r = q - N_LI; x = ra[2 * r]; y = ra[2 * r + 1]; }
            int xm = x - 1; if (xm < 0)      xm += GRIDW;
            int xp = x + 1; if (xp >= GRIDW) xp -= GRIDW;
            int ym = y - 1; if (ym < 0)      ym += GRIDW;
            int yp = y + 1; if (yp >= GRIDW) yp -= GRIDW;
            const float xa0 = (float)x,  xa1 = (float)xm, xa2 = (float)xp;
            const float yb0 = (float)y,  yb1 = (float)yp, yb2 = (float)ym;
            const float n2x0 = -2.0f * xa0, n2x1 = -2.0f * xa1, n2x2 = -2.0f * xa2;
            const float n2y0 = -2.0f * yb0, n2y1 = -2.0f * yb1, n2y2 = -2.0f * yb2;
            float mn[9];
            #pragma unroll
            for (int j = 0; j < 9; j++) mn[j] = 3.0e38f;
            for (int k = lane; k < cc; k += 32) {
                const float4 c = g_cand[k];
                const float w0 = fmaf(n2y0, c.y, c.z);
                const float w1 = fmaf(n2y1, c.y, c.z);
                const float w2 = fmaf(n2y2, c.y, c.z);
                mn[0] = fminf(mn[0], fmaf(n2x0, c.x, w0));
                mn[1] = fminf(mn[1], fmaf(n2x1, c.x, w0));
                mn[2] = fminf(mn[2], fmaf(n2x2, c.x, w0));
                mn[3] = fminf(mn[3], fmaf(n2x0, c.x, w1));
                mn[4] = fminf(mn[4], fmaf(n2x1, c.x, w1));
                mn[5] = fminf(mn[5], fmaf(n2x2, c.x, w1));
                mn[6] = fminf(mn[6], fmaf(n2x0, c.x, w2));
                mn[7] = fminf(mn[7], fmaf(n2x1, c.x, w2));
                mn[8] = fminf(mn[8], fmaf(n2x2, c.x, w2));
            }
            #pragma unroll
            for (int j = 0; j < 9; j++) {
                float v = mn[j];
                #pragma unroll
                for (int o = 16; o; o >>= 1) v = fminf(v, __shfl_xor_sync(FULL, v, o));
                mn[j] = v;
            }
            if (lane == 0) {
                const float x2[3] = {xa0 * xa0, xa1 * xa1, xa2 * xa2};
                const float y2[3] = {yb0 * yb0, yb1 * yb1, yb2 * yb2};
                float* o = out + (size_t)q * 9;
                #pragma unroll
                for (int j = 0; j < 9; j++) {
                    float d2 = mn[j] + x2[j % 3] + y2[j / 3];
                    o[j] = active ? 0.01f * sqrtf(fmaxf(d2, 0.0f)) : 0.0f;
                }
            }
        }
    }
}

extern "C" void kernel_launch(void* const* d_in, const int* in_sizes, int n_in,
                              void* d_out, int out_size) {
    const int*   li  = (const int*)d_in[0];
    const int*   ra  = (const int*)d_in[1];
    const float* pts = (const float*)d_in[2];
    const int*   vox = (const int*)d_in[3];
    float* out = (float*)d_out;
    k1_prep<<<SEGS + 1 + TILES, 256>>>(li, ra, pts, vox);
    k2_main<<<TILES + SLOW_BLOCKS, 256>>>(li, ra, out);
}